// round 11
// baseline (speedup 1.0000x reference)
#include <cuda_runtime.h>
#include <cuda_bf16.h>

using u32 = unsigned int;
using u64 = unsigned long long;

// Problem constants (fixed by setup_inputs)
constexpr int B = 4, S = 4096, D = 256, M = 256, H = 8;
constexpr int SK = 8;                   // split-K chunks for ctx GEMM
constexpr float LNEPS = 1e-5f;
constexpr float KEPS  = 1e-4f;
constexpr float DN    = 0.25f;          // 256^-0.25
constexpr float RATIO = 0.0625f;        // 256^-0.5

// ---------------- device scratch (no allocation APIs allowed) --------------
__device__ float g_xn[B * S * D];                 // layernormed x (= v), fp32
__device__ float g_diag[B * S];
__device__ __nv_bfloat16 g_ah[B * S * D], g_al[B * S * D];   // split(DN*xn) [s,d]
__device__ __nv_bfloat16 g_pbh[M * D],   g_pbl[M * D];       // split(proj)  [m,d]
__device__ __nv_bfloat16 g_vth[B * D * S], g_vtl[B * D * S]; // split(xn^T)  [d,s]
__device__ float g_pd[B * S * M];                 // projection, fp32
__device__ float g_rowmax[B * S];                 // atomicMax targets
__device__ float g_bmax[B];
__device__ __nv_bfloat16 g_qh[B * S * M], g_ql[B * S * M];   // split(q)  [s,m]
__device__ __nv_bfloat16 g_kth[B * M * S], g_ktl[B * M * S]; // split(k^T)[m,s]
__device__ float g_pksum[B * (S / 64) * M];
__device__ float g_ksum[B * M];
__device__ float g_pctx[B * SK * M * D];          // split-K ctx partials
__device__ __nv_bfloat16 g_cth[B * D * M], g_ctl[B * D * M]; // split(ctx^T)[d,m]

// ---------------- PTX helpers (plain sm_103-safe: mma.sync/ldmatrix/cp.async)
__device__ __forceinline__ u32 s2u(const void* p) {
    u32 a;
    asm("{ .reg .u64 t; cvta.to.shared.u64 t, %1; cvt.u32.u64 %0, t; }"
        : "=r"(a) : "l"(p));
    return a;
}
#define LDM4(r, a) \
    asm volatile("ldmatrix.sync.aligned.m8n8.x4.shared.b16 {%0,%1,%2,%3}, [%4];" \
        : "=r"((r)[0]), "=r"((r)[1]), "=r"((r)[2]), "=r"((r)[3]) : "r"(a))
#define MMA(c, a, b0_, b1_) \
    asm volatile("mma.sync.aligned.m16n8k16.row.col.f32.bf16.bf16.f32 " \
        "{%0,%1,%2,%3}, {%4,%5,%6,%7}, {%8,%9}, {%0,%1,%2,%3};" \
        : "+f"((c)[0]), "+f"((c)[1]), "+f"((c)[2]), "+f"((c)[3]) \
        : "r"((a)[0]), "r"((a)[1]), "r"((a)[2]), "r"((a)[3]), "r"(b0_), "r"(b1_))
#define CP_ASYNC16(dst, src) \
    asm volatile("cp.async.cg.shared.global [%0], [%1], 16;" :: "r"(dst), "l"(src))
#define CP_COMMIT() asm volatile("cp.async.commit_group;" ::: "memory")

// smem stage geometry: 4 tiles (Ah,Al,Bh,Bl) of 128 rows x 64 bf16, padded to
// 144B/row (conflict-free ldmatrix), double buffered.
constexpr int TROW   = 144;                 // bytes per padded row
constexpr int TILEB  = 128 * TROW;          // 18432 B per tile
constexpr int STAGEB = 4 * TILEB;           // 73728 B per stage
constexpr int SMEM_MMA = 2 * STAGEB;        // 147456 B
constexpr int NPAD = 132;                   // epilogue fp32 row stride
constexpr int KSUM_OFF = 69632;             // smem offset of ksum buf (MODE 2)

__device__ __forceinline__ void split_store(__nv_bfloat16* hi, __nv_bfloat16* lo,
                                            size_t o, float v) {
    __nv_bfloat16 h = __float2bfloat16(v);
    hi[o] = h;
    lo[o] = __float2bfloat16(v - __bfloat162float(h));
}

// order-independent (deterministic) float atomic max
__device__ __forceinline__ void atomicMaxF(float* addr, float v) {
    if (v >= 0.0f) atomicMax((int*)addr, __float_as_int(v));
    else           atomicMin((u32*)addr, __float_as_uint(v));
}

// ============================================================
// K1 (fused): LayerNorm + diag + bf16 split of DN*xn + xn^T split
//             + proj split + rowmax/bmax init.  Blocks >= 512 do proj.
// ============================================================
__global__ void __launch_bounds__(256) k_pre(const float* __restrict__ x,
                                             const float* __restrict__ gamma,
                                             const float* __restrict__ beta,
                                             const float* __restrict__ proj) {
    const int t = threadIdx.x;
    if (blockIdx.x >= 512) {                 // proj split (32 blocks)
        const int pb = blockIdx.x - 512;
#pragma unroll
        for (int it = 0; it < 8; it++) {
            const int i = pb * 2048 + it * 256 + t;
            split_store(g_pbh, g_pbl, i, proj[i]);
        }
        if (pb == 0 && t < B) g_bmax[t] = __int_as_float(0xFF800000);
        return;
    }
    const int b = blockIdx.x >> 7;           // 128 blocks per batch
    const int s0 = (blockIdx.x & 127) * 32;
    __shared__ float xs[32][257];
    __shared__ float mu_s[32], rs_s[32];
    const float gm = gamma[t], bt = beta[t];
    const int w = t >> 5, lane = t & 31;
#pragma unroll 4
    for (int r = 0; r < 32; r++)
        xs[r][t] = x[((size_t)b * S + s0 + r) * D + t];
    __syncthreads();
#pragma unroll
    for (int rr = 0; rr < 4; rr++) {         // warp w owns rows 4w..4w+3
        const int row = w * 4 + rr;
        float a = 0.f, q = 0.f;
#pragma unroll
        for (int i = 0; i < 8; i++) {
            const float v = xs[row][lane + i * 32];
            a += v; q += v * v;
        }
#pragma unroll
        for (int o = 16; o; o >>= 1) {
            a += __shfl_xor_sync(~0u, a, o);
            q += __shfl_xor_sync(~0u, q, o);
        }
        if (lane == 0) {
            const float mu = a * (1.0f / D);
            mu_s[row] = mu;
            rs_s[row] = rsqrtf(q * (1.0f / D) - mu * mu + LNEPS);
        }
    }
    __syncthreads();
#pragma unroll 4
    for (int r = 0; r < 32; r++) {
        const float xv = (xs[r][t] - mu_s[r]) * rs_s[r] * gm + bt;
        const size_t o = ((size_t)b * S + s0 + r) * D + t;
        g_xn[o] = xv;
        split_store(g_ah, g_al, o, DN * xv);
        xs[r][t] = xv;
    }
    __syncthreads();
#pragma unroll
    for (int rr = 0; rr < 4; rr++) {         // diag per row
        const int row = w * 4 + rr;
        float q = 0.f;
#pragma unroll
        for (int i = 0; i < 8; i++) {
            const float v = xs[row][lane + i * 32];
            q += v * v;
        }
#pragma unroll
        for (int o = 16; o; o >>= 1) q += __shfl_xor_sync(~0u, q, o);
        if (lane == 0) g_diag[b * S + s0 + row] = q * (0.5f * DN * DN);
    }
    if (t < 32) g_rowmax[b * S + s0 + t] = __int_as_float(0xFF800000);
    // transposed vT split: thread t = column d, 4 rows packed per u64 store
#pragma unroll
    for (int g = 0; g < 8; g++) {
        __nv_bfloat16 h4[4], l4[4];
#pragma unroll
        for (int j = 0; j < 4; j++) {
            const float v = xs[g * 4 + j][t];
            h4[j] = __float2bfloat16(v);
            l4[j] = __float2bfloat16(v - __bfloat162float(h4[j]));
        }
        const size_t o = ((size_t)b * D + t) * S + s0 + g * 4;
        *(u64*)(g_vth + o) = *(const u64*)h4;
        *(u64*)(g_vtl + o) = *(const u64*)l4;
    }
}

// ============================================================
// Core mma.sync GEMM: D[128x128] = sum (Ah+Al) @ (Bh+Bl)^T  (bf16x3)
// MODE 0: pd = (DN*xn) @ proj^T   (+ rowmax/bmax atomics)
// MODE 1: pctx[sk] = k^T @ v^T^T  (split-K over 512 s-rows)
// MODE 2: out = dinv * (q @ ctx^T^T)  (dinv inline, x8 head broadcast)
// ============================================================
template <int MODE>
__global__ void __launch_bounds__(256) k_mma(float* __restrict__ gout) {
    extern __shared__ char sm[];
    const u32 smb = s2u(sm);
    const int t = threadIdx.x, wid = t >> 5, lane = t & 31;
    constexpr int NCH = (MODE == 1) ? 8 : 4;   // K chunks of 64

    int b, row0, col0, ldA, ldB, sk = 0;
    const __nv_bfloat16 *Ah, *Al, *Bh, *Bl;
    if constexpr (MODE == 0) {
        b = blockIdx.z; row0 = blockIdx.x * 128; col0 = blockIdx.y * 128;
        ldA = D; ldB = D;
        const size_t ao = ((size_t)b * S + row0) * D;
        Ah = g_ah + ao; Al = g_al + ao;
        const size_t bo = (size_t)col0 * D;
        Bh = g_pbh + bo; Bl = g_pbl + bo;
    } else if constexpr (MODE == 1) {
        b = blockIdx.z / SK; sk = blockIdx.z % SK;
        row0 = blockIdx.x * 128; col0 = blockIdx.y * 128;
        ldA = S; ldB = S;
        const size_t ao = ((size_t)b * M + row0) * S + sk * (S / SK);
        Ah = g_kth + ao; Al = g_ktl + ao;
        const size_t bo = ((size_t)b * D + col0) * S + sk * (S / SK);
        Bh = g_vth + bo; Bl = g_vtl + bo;
    } else {
        b = blockIdx.z; row0 = blockIdx.x * 128; col0 = blockIdx.y * 128;
        ldA = M; ldB = M;
        const size_t ao = ((size_t)b * S + row0) * M;
        Ah = g_qh + ao; Al = g_ql + ao;
        const size_t bo = ((size_t)b * D + col0) * M;
        Bh = g_cth + bo; Bl = g_ctl + bo;
    }

    auto load_stage = [&](int ch, int st) {
        const __nv_bfloat16* srcs[4] = {Ah + ch * 64, Al + ch * 64,
                                        Bh + ch * 64, Bl + ch * 64};
#pragma unroll
        for (int it = 0; it < 16; it++) {
            const int idx = it * 256 + t;
            const int tile = idx >> 10, rem = idx & 1023;
            const int r = rem >> 3, c = rem & 7;
            const __nv_bfloat16* src =
                srcs[tile] + (size_t)r * ((tile < 2) ? ldA : ldB) + c * 8;
            const u32 dst = smb + st * STAGEB + tile * TILEB + r * TROW + c * 16;
            CP_ASYNC16(dst, src);
        }
        CP_COMMIT();
    };

    load_stage(0, 0);

    const int wm = wid >> 1, wn = wid & 1;     // warp tile 32(m) x 64(n)
    const u32 aoff = (u32)((lane & 15) * TROW + (lane >> 4) * 16);
    const u32 boff = (u32)(((lane & 7) + ((lane >> 4) & 1) * 8) * TROW +
                           ((lane >> 3) & 1) * 16);
    float acc[2][8][4] = {};

    for (int ch = 0; ch < NCH; ch++) {
        const int st = ch & 1;
        if (ch < NCH - 1) {
            load_stage(ch + 1, st ^ 1);
            asm volatile("cp.async.wait_group 1;" ::: "memory");
        } else {
            asm volatile("cp.async.wait_group 0;" ::: "memory");
        }
        __syncthreads();
        const u32 sA = smb + st * STAGEB;
        const u32 sAh = sA, sAl = sA + TILEB;
        const u32 sBh = sA + 2 * TILEB, sBl = sA + 3 * TILEB;
#pragma unroll
        for (int ks = 0; ks < 4; ks++) {
            u32 ah[2][4], al[2][4], bh[4][4], bl[4][4];
#pragma unroll
            for (int mi = 0; mi < 2; mi++) {
                const u32 a = (u32)((wm * 32 + mi * 16) * TROW + ks * 32) + aoff;
                LDM4(ah[mi], sAh + a);
                LDM4(al[mi], sAl + a);
            }
#pragma unroll
            for (int g = 0; g < 4; g++) {
                const u32 a = (u32)((wn * 64 + g * 16) * TROW + ks * 32) + boff;
                LDM4(bh[g], sBh + a);
                LDM4(bl[g], sBl + a);
            }
#pragma unroll
            for (int mi = 0; mi < 2; mi++)
#pragma unroll
                for (int g = 0; g < 4; g++) {
                    MMA(acc[mi][2 * g],     ah[mi], bh[g][0], bh[g][1]);
                    MMA(acc[mi][2 * g + 1], ah[mi], bh[g][2], bh[g][3]);
                    MMA(acc[mi][2 * g],     ah[mi], bl[g][0], bl[g][1]);
                    MMA(acc[mi][2 * g + 1], ah[mi], bl[g][2], bl[g][3]);
                    MMA(acc[mi][2 * g],     al[mi], bh[g][0], bh[g][1]);
                    MMA(acc[mi][2 * g + 1], al[mi], bh[g][2], bh[g][3]);
                }
        }
        __syncthreads();
    }

    // MODE 2: inline dinv[row] = 1 / dot(q[row,:], ksum)
    float dv_val = 1.0f;
    if constexpr (MODE == 2) {
        float* ksm = (float*)(sm + KSUM_OFF);
        ksm[t] = g_ksum[b * M + t];
        __syncthreads();
        const int drow = t >> 1, dhalf = t & 1;
        const size_t qo = ((size_t)b * S + row0 + drow) * M + dhalf * 128;
        float dacc = 0.f;
#pragma unroll 4
        for (int j = 0; j < 128; j++)
            dacc += (__bfloat162float(g_qh[qo + j]) +
                     __bfloat162float(g_ql[qo + j])) * ksm[dhalf * 128 + j];
        dacc += __shfl_xor_sync(~0u, dacc, 1);
        dv_val = 1.0f / dacc;
    }

    // Epilogue: fragments -> smem (fp32, NPAD stride) -> coalesced stores
    float* ep = (float*)sm;
#pragma unroll
    for (int mi = 0; mi < 2; mi++)
#pragma unroll
        for (int g = 0; g < 8; g++) {
            const int row = wm * 32 + mi * 16 + (lane >> 2);
            const int col = wn * 64 + g * 8 + (lane & 3) * 2;
            *(float2*)&ep[row * NPAD + col] =
                make_float2(acc[mi][g][0], acc[mi][g][1]);
            *(float2*)&ep[(row + 8) * NPAD + col] =
                make_float2(acc[mi][g][2], acc[mi][g][3]);
        }
    __syncthreads();

    const int row = t >> 1, half = t & 1, c0 = half * 64;
    const float* er = ep + row * NPAD + c0;
    if constexpr (MODE == 0) {
        float mx = -1e30f;
        const size_t o = ((size_t)b * S + row0 + row) * M + col0 + c0;
#pragma unroll
        for (int j = 0; j < 16; j++) {
            const float4 v = *(const float4*)(er + j * 4);
            mx = fmaxf(mx, fmaxf(fmaxf(v.x, v.y), fmaxf(v.z, v.w)));
            *(float4*)(g_pd + o + j * 4) = v;
        }
        mx = fmaxf(mx, __shfl_xor_sync(~0u, mx, 1));   // full 128-col tile max
        if (half == 0) atomicMaxF(&g_rowmax[b * S + row0 + row], mx);
        // block-level bmax: warp reduce then single atomic
        float bmx = mx;
#pragma unroll
        for (int o2 = 16; o2; o2 >>= 1)
            bmx = fmaxf(bmx, __shfl_xor_sync(~0u, bmx, o2));
        __shared__ float wred[8];
        if (lane == 0) wred[wid] = bmx;
        __syncthreads();
        if (t == 0) {
            float m2 = wred[0];
#pragma unroll
            for (int i = 1; i < 8; i++) m2 = fmaxf(m2, wred[i]);
            atomicMaxF(&g_bmax[b], m2);
        }
    } else if constexpr (MODE == 1) {
        const size_t o =
            (((size_t)(b * SK + sk)) * M + row0 + row) * D + col0 + c0;
#pragma unroll
        for (int j = 0; j < 16; j++)
            *(float4*)(g_pctx + o + j * 4) = *(const float4*)(er + j * 4);
    } else {
        const size_t o = ((size_t)b * H * S + row0 + row) * D + col0 + c0;
#pragma unroll
        for (int j = 0; j < 16; j++) {
            float4 v = *(const float4*)(er + j * 4);
            v.x *= dv_val; v.y *= dv_val; v.z *= dv_val; v.w *= dv_val;
#pragma unroll
            for (int h = 0; h < H; h++)
                *(float4*)(gout + o + (size_t)h * S * D + j * 4) = v;
        }
    }
}

// ============================================================
// K3: exp pass — q (split, [s,m]), k^T (split, [m,s]), ksum partials
// 64x64 tiles, grid (S/64, M/64, B)
// ============================================================
__global__ void __launch_bounds__(256) k_kexp() {
    const int b = blockIdx.z, s0 = blockIdx.x * 64, m0 = blockIdx.y * 64;
    const int t = threadIdx.x;
    __shared__ float kk[64][65];
    __shared__ float dm[64], fr[64];
    if (t < 64) {
        const int s = s0 + t;
        const float rm = g_rowmax[b * S + s];
        dm[t] = g_diag[b * S + s] + rm;
        fr[t] = __expf(rm - g_bmax[b]);
    }
    __syncthreads();
#pragma unroll
    for (int it = 0; it < 16; it++) {
        const int idx = it * 256 + t, r = idx >> 6, c = idx & 63;
        const float pdv = g_pd[((size_t)b * S + s0 + r) * M + m0 + c];
        const float e = __expf(pdv - dm[r]);
        split_store(g_qh, g_ql, ((size_t)b * S + s0 + r) * M + m0 + c,
                    RATIO * e + RATIO * KEPS);
        kk[r][c] = RATIO * e * fr[r] + RATIO * KEPS;
    }
    __syncthreads();
#pragma unroll
    for (int it = 0; it < 16; it++) {
        const int idx = it * 256 + t, mr = idx >> 6, sc = idx & 63;
        split_store(g_kth, g_ktl, ((size_t)b * M + m0 + mr) * S + s0 + sc,
                    kk[sc][mr]);
    }
    if (t < 64) {
        float s = 0.f;
#pragma unroll
        for (int i = 0; i < 64; i++) s += kk[i][t];
        g_pksum[((size_t)b * (S / 64) + blockIdx.x) * M + m0 + t] = s;
    }
}

// ============================================================
// K5: reduce ctx partials + transpose + bf16 split -> ctx^T [d,m]
//     (+ ksum reduction on the by==0 slice)
// ============================================================
__global__ void __launch_bounds__(256) k_ctxred() {
    const int b = blockIdx.z, m0 = blockIdx.x * 32, d0 = blockIdx.y * 32;
    __shared__ float sm[32][33];
    const int t = threadIdx.x;
#pragma unroll
    for (int it = 0; it < 4; it++) {
        const int idx = it * 256 + t, mr = idx >> 5, dc = idx & 31;
        float s = 0.f;
#pragma unroll
        for (int sk = 0; sk < SK; sk++)
            s += g_pctx[(((size_t)(b * SK + sk)) * M + m0 + mr) * D + d0 + dc];
        sm[mr][dc] = s;
    }
    __syncthreads();
#pragma unroll
    for (int it = 0; it < 4; it++) {
        const int idx = it * 256 + t, dr = idx >> 5, mc = idx & 31;
        split_store(g_cth, g_ctl, ((size_t)b * D + d0 + dr) * M + m0 + mc,
                    sm[mc][dr]);
    }
    if (blockIdx.y == 0 && t < 32) {
        float s = 0.f;
#pragma unroll
        for (int st = 0; st < S / 64; st++)
            s += g_pksum[((size_t)b * (S / 64) + st) * M + m0 + t];
        g_ksum[b * M + m0 + t] = s;
    }
}

extern "C" void kernel_launch(void* const* d_in, const int* in_sizes, int n_in,
                              void* d_out, int out_size) {
    const float* x     = (const float*)d_in[0];
    const float* gamma = (const float*)d_in[1];
    const float* beta  = (const float*)d_in[2];
    const float* proj  = (const float*)d_in[3];
    float* out = (float*)d_out;
    (void)in_sizes; (void)n_in; (void)out_size;

    cudaFuncSetAttribute(k_mma<0>, cudaFuncAttributeMaxDynamicSharedMemorySize, SMEM_MMA);
    cudaFuncSetAttribute(k_mma<1>, cudaFuncAttributeMaxDynamicSharedMemorySize, SMEM_MMA);
    cudaFuncSetAttribute(k_mma<2>, cudaFuncAttributeMaxDynamicSharedMemorySize, SMEM_MMA);

    k_pre<<<544, 256>>>(x, gamma, beta, proj);
    k_mma<0><<<dim3(S / 128, M / 128, B), 256, SMEM_MMA>>>(nullptr);
    k_kexp<<<dim3(S / 64, M / 64, B), 256>>>();
    k_mma<1><<<dim3(M / 128, D / 128, B * SK), 256, SMEM_MMA>>>(nullptr);
    k_ctxred<<<dim3(M / 32, D / 32, B), 256>>>();
    k_mma<2><<<dim3(S / 128, D / 128, B), 256, SMEM_MMA>>>(out);
}

// round 12
// speedup vs baseline: 1.3730x; 1.3730x over previous
#include <cuda_runtime.h>
#include <cuda_bf16.h>

using u32 = unsigned int;
using u64 = unsigned long long;

// Problem constants (fixed by setup_inputs)
constexpr int B = 4, S = 4096, D = 256, M = 256, H = 8;
constexpr int SK = 16;                  // split-K chunks for ctx GEMM
constexpr float LNEPS = 1e-5f;
constexpr float KEPS  = 1e-4f;
constexpr float DN    = 0.25f;          // 256^-0.25
constexpr float RATIO = 0.0625f;        // 256^-0.5

// ---------------- device scratch (no allocation APIs allowed) --------------
__device__ float g_diag[B * S];
__device__ __nv_bfloat16 g_ah[B * S * D], g_al[B * S * D];   // split(DN*xn) [s,d]
__device__ __nv_bfloat16 g_pbh[M * D],   g_pbl[M * D];       // split(proj)  [m,d]
__device__ __nv_bfloat16 g_vth[B * D * S], g_vtl[B * D * S]; // split(xn^T)  [d,s]
__device__ float g_pd[B * S * M];                 // projection, fp32
__device__ float g_rowmax[B * S];                 // atomicMax targets
__device__ float g_bmax[B];
__device__ __nv_bfloat16 g_qh[B * S * M], g_ql[B * S * M];   // split(q)  [s,m]
__device__ __nv_bfloat16 g_kth[B * M * S], g_ktl[B * M * S]; // split(k^T)[m,s]
__device__ float g_pksum[B * (S / 64) * M];
__device__ float g_ksum[B * M];
__device__ float g_pctx[B * SK * M * D];          // split-K ctx partials
__device__ __nv_bfloat16 g_cth[B * D * M], g_ctl[B * D * M]; // split(ctx^T)[d,m]

// ---------------- PTX helpers (plain sm_103-safe: mma.sync/ldmatrix/cp.async)
__device__ __forceinline__ u32 s2u(const void* p) {
    u32 a;
    asm("{ .reg .u64 t; cvta.to.shared.u64 t, %1; cvt.u32.u64 %0, t; }"
        : "=r"(a) : "l"(p));
    return a;
}
#define LDM4(r, a) \
    asm volatile("ldmatrix.sync.aligned.m8n8.x4.shared.b16 {%0,%1,%2,%3}, [%4];" \
        : "=r"((r)[0]), "=r"((r)[1]), "=r"((r)[2]), "=r"((r)[3]) : "r"(a))
#define MMA(c, a, b0_, b1_) \
    asm volatile("mma.sync.aligned.m16n8k16.row.col.f32.bf16.bf16.f32 " \
        "{%0,%1,%2,%3}, {%4,%5,%6,%7}, {%8,%9}, {%0,%1,%2,%3};" \
        : "+f"((c)[0]), "+f"((c)[1]), "+f"((c)[2]), "+f"((c)[3]) \
        : "r"((a)[0]), "r"((a)[1]), "r"((a)[2]), "r"((a)[3]), "r"(b0_), "r"(b1_))
#define CP_ASYNC16(dst, src) \
    asm volatile("cp.async.cg.shared.global [%0], [%1], 16;" :: "r"(dst), "l"(src))
#define CP_COMMIT() asm volatile("cp.async.commit_group;" ::: "memory")

// smem stage geometry: 4 tiles (Ah,Al,Bh,Bl) of 128 rows x 64 bf16, padded to
// 144B/row (conflict-free ldmatrix), double buffered. +1KB ksum buffer.
constexpr int TROW   = 144;                 // bytes per padded row
constexpr int TILEB  = 128 * TROW;          // 18432 B per tile
constexpr int STAGEB = 4 * TILEB;           // 73728 B per stage
constexpr int SMEM_MMA = 2 * STAGEB + 1024; // 148480 B
constexpr int KSUM_OFF = 2 * STAGEB;        // ksum buffer (MODE 2)
constexpr int NPAD = 132;                   // epilogue fp32 row stride

__device__ __forceinline__ void split_store(__nv_bfloat16* hi, __nv_bfloat16* lo,
                                            size_t o, float v) {
    __nv_bfloat16 h = __float2bfloat16(v);
    hi[o] = h;
    lo[o] = __float2bfloat16(v - __bfloat162float(h));
}

// order-independent (deterministic) float atomic max
__device__ __forceinline__ void atomicMaxF(float* addr, float v) {
    if (v >= 0.0f) atomicMax((int*)addr, __float_as_int(v));
    else           atomicMin((u32*)addr, __float_as_uint(v));
}

// ============================================================
// K1 (fused): LayerNorm + diag + bf16 split of DN*xn + xn^T split
//             + proj split + rowmax/bmax init.  Blocks >= 512 do proj.
// ============================================================
__global__ void __launch_bounds__(256) k_pre(const float* __restrict__ x,
                                             const float* __restrict__ gamma,
                                             const float* __restrict__ beta,
                                             const float* __restrict__ proj) {
    const int t = threadIdx.x;
    if (blockIdx.x >= 512) {                 // proj split (32 blocks)
        const int pb = blockIdx.x - 512;
#pragma unroll
        for (int it = 0; it < 8; it++) {
            const int i = pb * 2048 + it * 256 + t;
            split_store(g_pbh, g_pbl, i, proj[i]);
        }
        if (pb == 0 && t < B) g_bmax[t] = __int_as_float(0xFF800000);
        return;
    }
    const int b = blockIdx.x >> 7;           // 128 blocks per batch
    const int s0 = (blockIdx.x & 127) * 32;
    __shared__ float xs[32][257];
    __shared__ float mu_s[32], rs_s[32];
    const float gm = gamma[t], bt = beta[t];
    const int w = t >> 5, lane = t & 31;
#pragma unroll 4
    for (int r = 0; r < 32; r++)
        xs[r][t] = x[((size_t)b * S + s0 + r) * D + t];
    __syncthreads();
#pragma unroll
    for (int rr = 0; rr < 4; rr++) {         // warp w owns rows 4w..4w+3
        const int row = w * 4 + rr;
        float a = 0.f, q = 0.f;
#pragma unroll
        for (int i = 0; i < 8; i++) {
            const float v = xs[row][lane + i * 32];
            a += v; q += v * v;
        }
#pragma unroll
        for (int o = 16; o; o >>= 1) {
            a += __shfl_xor_sync(~0u, a, o);
            q += __shfl_xor_sync(~0u, q, o);
        }
        if (lane == 0) {
            const float mu = a * (1.0f / D);
            mu_s[row] = mu;
            rs_s[row] = rsqrtf(q * (1.0f / D) - mu * mu + LNEPS);
        }
    }
    __syncthreads();
#pragma unroll 4
    for (int r = 0; r < 32; r++) {
        const float xv = (xs[r][t] - mu_s[r]) * rs_s[r] * gm + bt;
        split_store(g_ah, g_al, ((size_t)b * S + s0 + r) * D + t, DN * xv);
        xs[r][t] = xv;
    }
    __syncthreads();
#pragma unroll
    for (int rr = 0; rr < 4; rr++) {         // diag per row
        const int row = w * 4 + rr;
        float q = 0.f;
#pragma unroll
        for (int i = 0; i < 8; i++) {
            const float v = xs[row][lane + i * 32];
            q += v * v;
        }
#pragma unroll
        for (int o = 16; o; o >>= 1) q += __shfl_xor_sync(~0u, q, o);
        if (lane == 0) g_diag[b * S + s0 + row] = q * (0.5f * DN * DN);
    }
    if (t < 32) g_rowmax[b * S + s0 + t] = __int_as_float(0xFF800000);
    // transposed vT split: thread t = column d, 4 rows packed per u64 store
#pragma unroll
    for (int g = 0; g < 8; g++) {
        __nv_bfloat16 h4[4], l4[4];
#pragma unroll
        for (int j = 0; j < 4; j++) {
            const float v = xs[g * 4 + j][t];
            h4[j] = __float2bfloat16(v);
            l4[j] = __float2bfloat16(v - __bfloat162float(h4[j]));
        }
        const size_t o = ((size_t)b * D + t) * S + s0 + g * 4;
        *(u64*)(g_vth + o) = *(const u64*)h4;
        *(u64*)(g_vtl + o) = *(const u64*)l4;
    }
}

// ============================================================
// Core mma.sync GEMM, 512 threads, 16 warps (32x32 warp tiles on 128x128)
// MODE 0: pd = (DN*xn) @ proj^T   (+ rowmax/bmax atomics)
// MODE 1: pctx[sk] = k^T @ v^T^T  (split-K over 256 s-rows, SK=16)
// MODE 2: out = dinv * (q @ ctx^T^T)  (dinv from staged q tiles, x8 heads)
// ============================================================
template <int MODE>
__global__ void __launch_bounds__(512) k_mma(float* __restrict__ gout) {
    extern __shared__ char sm[];
    const u32 smb = s2u(sm);
    const int t = threadIdx.x, wid = t >> 5, lane = t & 31;
    constexpr int NCH = 4;                 // K = 256 = 4 chunks of 64

    int b, row0, col0, ldA, ldB, sk = 0;
    const __nv_bfloat16 *Ah, *Al, *Bh, *Bl;
    if constexpr (MODE == 0) {
        b = blockIdx.z; row0 = blockIdx.x * 128; col0 = blockIdx.y * 128;
        ldA = D; ldB = D;
        const size_t ao = ((size_t)b * S + row0) * D;
        Ah = g_ah + ao; Al = g_al + ao;
        const size_t bo = (size_t)col0 * D;
        Bh = g_pbh + bo; Bl = g_pbl + bo;
    } else if constexpr (MODE == 1) {
        b = blockIdx.z / SK; sk = blockIdx.z % SK;
        row0 = blockIdx.x * 128; col0 = blockIdx.y * 128;
        ldA = S; ldB = S;
        const size_t ao = ((size_t)b * M + row0) * S + sk * (S / SK);
        Ah = g_kth + ao; Al = g_ktl + ao;
        const size_t bo = ((size_t)b * D + col0) * S + sk * (S / SK);
        Bh = g_vth + bo; Bl = g_vtl + bo;
    } else {
        b = blockIdx.z; row0 = blockIdx.x * 128; col0 = blockIdx.y * 128;
        ldA = M; ldB = M;
        const size_t ao = ((size_t)b * S + row0) * M;
        Ah = g_qh + ao; Al = g_ql + ao;
        const size_t bo = ((size_t)b * D + col0) * M;
        Bh = g_cth + bo; Bl = g_ctl + bo;
    }

    float* ksm = (float*)(sm + KSUM_OFF);
    if constexpr (MODE == 2) {
        if (t < 256) ksm[t] = g_ksum[b * M + t];
    }

    // stage loader: 4 tiles x 128 rows x 128B via 16B cp.async (8 per thread)
    auto load_stage = [&](int ch, int st) {
        const __nv_bfloat16* srcs[4] = {Ah + ch * 64, Al + ch * 64,
                                        Bh + ch * 64, Bl + ch * 64};
#pragma unroll
        for (int it = 0; it < 8; it++) {
            const int idx = it * 512 + t;
            const int tile = idx >> 10, rem = idx & 1023;
            const int r = rem >> 3, c = rem & 7;
            const __nv_bfloat16* src =
                srcs[tile] + (size_t)r * ((tile < 2) ? ldA : ldB) + c * 8;
            const u32 dst = smb + st * STAGEB + tile * TILEB + r * TROW + c * 16;
            CP_ASYNC16(dst, src);
        }
        CP_COMMIT();
    };

    load_stage(0, 0);

    const int wm = wid >> 2, wn = wid & 3;     // warp tile 32(m) x 32(n)
    const u32 aoff = (u32)((lane & 15) * TROW + (lane >> 4) * 16);
    const u32 boff = (u32)(((lane & 7) + ((lane >> 4) & 1) * 8) * TROW +
                           ((lane >> 3) & 1) * 16);
    float acc[2][4][4] = {};
    float dacc = 0.f;
    const int drow = t >> 2, dcs = (t & 3) * 16;   // dinv work split (MODE 2)

    for (int ch = 0; ch < NCH; ch++) {
        const int st = ch & 1;
        if (ch < NCH - 1) {
            load_stage(ch + 1, st ^ 1);
            asm volatile("cp.async.wait_group 1;" ::: "memory");
        } else {
            asm volatile("cp.async.wait_group 0;" ::: "memory");
        }
        __syncthreads();
        const u32 sA = smb + st * STAGEB;
        const u32 sAh = sA, sAl = sA + TILEB;
        const u32 sBh = sA + 2 * TILEB, sBl = sA + 3 * TILEB;
#pragma unroll
        for (int ks = 0; ks < 4; ks++) {
            u32 ah[2][4], al[2][4], bh[2][4], bl[2][4];
#pragma unroll
            for (int mi = 0; mi < 2; mi++) {
                const u32 a = (u32)((wm * 32 + mi * 16) * TROW + ks * 32) + aoff;
                LDM4(ah[mi], sAh + a);
                LDM4(al[mi], sAl + a);
            }
#pragma unroll
            for (int g = 0; g < 2; g++) {
                const u32 a = (u32)((wn * 32 + g * 16) * TROW + ks * 32) + boff;
                LDM4(bh[g], sBh + a);
                LDM4(bl[g], sBl + a);
            }
#pragma unroll
            for (int mi = 0; mi < 2; mi++)
#pragma unroll
                for (int g = 0; g < 2; g++) {
                    MMA(acc[mi][2 * g],     ah[mi], bh[g][0], bh[g][1]);
                    MMA(acc[mi][2 * g + 1], ah[mi], bh[g][2], bh[g][3]);
                    MMA(acc[mi][2 * g],     ah[mi], bl[g][0], bl[g][1]);
                    MMA(acc[mi][2 * g + 1], ah[mi], bl[g][2], bl[g][3]);
                    MMA(acc[mi][2 * g],     al[mi], bh[g][0], bh[g][1]);
                    MMA(acc[mi][2 * g + 1], al[mi], bh[g][2], bh[g][3]);
                }
        }
        if constexpr (MODE == 2) {
            // partial dot(q[drow,:], ksum) from the staged q tiles
            const __nv_bfloat16* qh =
                (const __nv_bfloat16*)(sm + st * STAGEB + drow * TROW) + dcs;
            const __nv_bfloat16* ql =
                (const __nv_bfloat16*)(sm + st * STAGEB + TILEB + drow * TROW) + dcs;
            const float* kv = ksm + ch * 64 + dcs;
#pragma unroll
            for (int j = 0; j < 16; j++)
                dacc += (__bfloat162float(qh[j]) + __bfloat162float(ql[j])) * kv[j];
        }
        __syncthreads();
    }

    float dv_val = 1.0f;
    if constexpr (MODE == 2) {
        dacc += __shfl_xor_sync(~0u, dacc, 1);
        dacc += __shfl_xor_sync(~0u, dacc, 2);
        dv_val = 1.0f / dacc;                  // valid for row = t>>2
    }

    // Epilogue: fragments -> smem (fp32, NPAD stride) -> coalesced stores
    float* ep = (float*)sm;
#pragma unroll
    for (int mi = 0; mi < 2; mi++)
#pragma unroll
        for (int g = 0; g < 4; g++) {
            const int row = wm * 32 + mi * 16 + (lane >> 2);
            const int col = wn * 32 + g * 8 + (lane & 3) * 2;
            *(float2*)&ep[row * NPAD + col] =
                make_float2(acc[mi][g][0], acc[mi][g][1]);
            *(float2*)&ep[(row + 8) * NPAD + col] =
                make_float2(acc[mi][g][2], acc[mi][g][3]);
        }
    __syncthreads();

    const int row = t >> 2, c0 = (t & 3) * 32;   // 32 cols per thread
    const float* er = ep + row * NPAD + c0;
    if constexpr (MODE == 0) {
        float mx = -1e30f;
        const size_t o = ((size_t)b * S + row0 + row) * M + col0 + c0;
#pragma unroll
        for (int j = 0; j < 8; j++) {
            const float4 v = *(const float4*)(er + j * 4);
            mx = fmaxf(mx, fmaxf(fmaxf(v.x, v.y), fmaxf(v.z, v.w)));
            *(float4*)(g_pd + o + j * 4) = v;
        }
        mx = fmaxf(mx, __shfl_xor_sync(~0u, mx, 1));
        mx = fmaxf(mx, __shfl_xor_sync(~0u, mx, 2));  // full 128-col tile max
        if ((t & 3) == 0) atomicMaxF(&g_rowmax[b * S + row0 + row], mx);
        float bmx = mx;
#pragma unroll
        for (int o2 = 16; o2; o2 >>= 1)
            bmx = fmaxf(bmx, __shfl_xor_sync(~0u, bmx, o2));
        __shared__ float wred[16];
        if (lane == 0) wred[wid] = bmx;
        __syncthreads();
        if (t == 0) {
            float m2 = wred[0];
#pragma unroll
            for (int i = 1; i < 16; i++) m2 = fmaxf(m2, wred[i]);
            atomicMaxF(&g_bmax[b], m2);
        }
    } else if constexpr (MODE == 1) {
        const size_t o =
            (((size_t)(b * SK + sk)) * M + row0 + row) * D + col0 + c0;
#pragma unroll
        for (int j = 0; j < 8; j++)
            *(float4*)(g_pctx + o + j * 4) = *(const float4*)(er + j * 4);
    } else {
        const size_t o = ((size_t)b * H * S + row0 + row) * D + col0 + c0;
#pragma unroll
        for (int j = 0; j < 8; j++) {
            float4 v = *(const float4*)(er + j * 4);
            v.x *= dv_val; v.y *= dv_val; v.z *= dv_val; v.w *= dv_val;
#pragma unroll
            for (int h = 0; h < H; h++)
                *(float4*)(gout + o + (size_t)h * S * D + j * 4) = v;
        }
    }
}

// ============================================================
// K3: exp pass — q (split, [s,m]), k^T (split, [m,s]), ksum partials
// 64x64 tiles, grid (S/64, M/64, B)
// ============================================================
__global__ void __launch_bounds__(256) k_kexp() {
    const int b = blockIdx.z, s0 = blockIdx.x * 64, m0 = blockIdx.y * 64;
    const int t = threadIdx.x;
    __shared__ float kk[64][65];
    __shared__ float dm[64], fr[64];
    if (t < 64) {
        const int s = s0 + t;
        const float rm = g_rowmax[b * S + s];
        dm[t] = g_diag[b * S + s] + rm;
        fr[t] = __expf(rm - g_bmax[b]);
    }
    __syncthreads();
#pragma unroll
    for (int it = 0; it < 16; it++) {
        const int idx = it * 256 + t, r = idx >> 6, c = idx & 63;
        const float pdv = g_pd[((size_t)b * S + s0 + r) * M + m0 + c];
        const float e = __expf(pdv - dm[r]);
        split_store(g_qh, g_ql, ((size_t)b * S + s0 + r) * M + m0 + c,
                    RATIO * e + RATIO * KEPS);
        kk[r][c] = RATIO * e * fr[r] + RATIO * KEPS;
    }
    __syncthreads();
#pragma unroll
    for (int it = 0; it < 16; it++) {
        const int idx = it * 256 + t, mr = idx >> 6, sc = idx & 63;
        split_store(g_kth, g_ktl, ((size_t)b * M + m0 + mr) * S + s0 + sc,
                    kk[sc][mr]);
    }
    if (t < 64) {
        float s = 0.f;
#pragma unroll
        for (int i = 0; i < 64; i++) s += kk[i][t];
        g_pksum[((size_t)b * (S / 64) + blockIdx.x) * M + m0 + t] = s;
    }
}

// ============================================================
// K5: reduce ctx partials + transpose + bf16 split -> ctx^T [d,m]
//     (+ ksum reduction on the by==0 slice)
// ============================================================
__global__ void __launch_bounds__(256) k_ctxred() {
    const int b = blockIdx.z, m0 = blockIdx.x * 32, d0 = blockIdx.y * 32;
    __shared__ float sm[32][33];
    const int t = threadIdx.x;
#pragma unroll
    for (int it = 0; it < 4; it++) {
        const int idx = it * 256 + t, mr = idx >> 5, dc = idx & 31;
        float s = 0.f;
#pragma unroll
        for (int sk = 0; sk < SK; sk++)
            s += g_pctx[(((size_t)(b * SK + sk)) * M + m0 + mr) * D + d0 + dc];
        sm[mr][dc] = s;
    }
    __syncthreads();
#pragma unroll
    for (int it = 0; it < 4; it++) {
        const int idx = it * 256 + t, dr = idx >> 5, mc = idx & 31;
        split_store(g_cth, g_ctl, ((size_t)b * D + d0 + dr) * M + m0 + mc,
                    sm[mc][dr]);
    }
    if (blockIdx.y == 0 && t < 32) {
        float s = 0.f;
#pragma unroll
        for (int st = 0; st < S / 64; st++)
            s += g_pksum[((size_t)b * (S / 64) + st) * M + m0 + t];
        g_ksum[b * M + m0 + t] = s;
    }
}

extern "C" void kernel_launch(void* const* d_in, const int* in_sizes, int n_in,
                              void* d_out, int out_size) {
    const float* x     = (const float*)d_in[0];
    const float* gamma = (const float*)d_in[1];
    const float* beta  = (const float*)d_in[2];
    const float* proj  = (const float*)d_in[3];
    float* out = (float*)d_out;
    (void)in_sizes; (void)n_in; (void)out_size;

    cudaFuncSetAttribute(k_mma<0>, cudaFuncAttributeMaxDynamicSharedMemorySize, SMEM_MMA);
    cudaFuncSetAttribute(k_mma<1>, cudaFuncAttributeMaxDynamicSharedMemorySize, SMEM_MMA);
    cudaFuncSetAttribute(k_mma<2>, cudaFuncAttributeMaxDynamicSharedMemorySize, SMEM_MMA);

    k_pre<<<544, 256>>>(x, gamma, beta, proj);
    k_mma<0><<<dim3(S / 128, M / 128, B), 512, SMEM_MMA>>>(nullptr);
    k_kexp<<<dim3(S / 64, M / 64, B), 256>>>();
    k_mma<1><<<dim3(M / 128, D / 128, B * SK), 512, SMEM_MMA>>>(nullptr);
    k_ctxred<<<dim3(M / 32, D / 32, B), 256>>>();
    k_mma<2><<<dim3(S / 128, D / 128, B), 512, SMEM_MMA>>>(out);
}